// round 7
// baseline (speedup 1.0000x reference)
#include <cuda_runtime.h>
#include <cstdint>

// Bilinear attention B=8, S=2048, H=1024 fp32, warp-level tf32 HMMA, 3xTF32.
// R7: 512 threads (16 warps, 4/SMSP) for latency hiding; warp tile 64x32;
// A-fragment register reuse keeps regs <= 128 so 512 threads fit one SM.
// GEMM1 (xw=x@W), GEMM2 (scores): 3 terms. GEMM3 (ctx=attn@x): 2 terms.

// ---------------- scratch (device globals; no allocation) ----------------
#define NBS (8ull * 2048ull * 1024ull)
__device__ float g_xh [NBS], g_xl [NBS];    // split x    [B,S,H]
__device__ float g_xth[NBS], g_xtl[NBS];    // split x^T  [B,H,S]
__device__ float g_wth[1024ull * 1024ull], g_wtl[1024ull * 1024ull];  // W^T
__device__ float g_xwh[NBS], g_xwl[NBS];    // split xw   [B,S,H]

// ---------------- helpers ----------------
__device__ __forceinline__ uint32_t smem_u32(const void* p) {
    uint32_t a;
    asm("{ .reg .u64 t; cvta.to.shared.u64 t, %1; cvt.u32.u64 %0, t; }" : "=r"(a) : "l"(p));
    return a;
}

#define CP_ASYNC16(dst, src) \
    asm volatile("cp.async.cg.shared.global [%0], [%1], 16;" :: "r"(dst), "l"(src) : "memory")
#define CP_COMMIT() asm volatile("cp.async.commit_group;" ::: "memory")
#define CP_WAIT(n)  asm volatile("cp.async.wait_group %0;" :: "n"(n) : "memory")

__device__ __forceinline__ float2 splitf(float v) {
    float h = __uint_as_float(__float_as_uint(v) & 0xFFFFE000u);
    uint32_t lo;
    asm("cvt.rna.tf32.f32 %0, %1;" : "=r"(lo) : "f"(v - h));
    return make_float2(h, __uint_as_float(lo));
}

__device__ __forceinline__ void mma8(float* c, const uint32_t* a, const uint32_t* b) {
    asm volatile(
        "mma.sync.aligned.m16n8k8.row.col.f32.tf32.tf32.f32 "
        "{%0,%1,%2,%3}, {%4,%5,%6,%7}, {%8,%9}, {%0,%1,%2,%3};"
        : "+f"(c[0]), "+f"(c[1]), "+f"(c[2]), "+f"(c[3])
        : "r"(a[0]), "r"(a[1]), "r"(a[2]), "r"(a[3]), "r"(b[0]), "r"(b[1]));
}

// ---------------- GEMM: C[m,n] = sum_k A[m,k] * B[n,k] ----------------
// CTA 128x256, K-chunk 32, 2-stage cp.async. 16 warps (2M x 8N), warp 64x32.
#define PAD   36
#define ATILB (128 * PAD * 4)   // 18432 B
#define BTILB (256 * PAD * 4)   // 36864 B

template <int TERMS, bool ASPLIT, bool CSPLIT>
__global__ __launch_bounds__(512, 1)
void gemm_tc(const float* __restrict__ Ahg, const float* __restrict__ Alg,
             const float* __restrict__ Bhg, const float* __restrict__ Blg,
             float* __restrict__ Cg, float* __restrict__ C2g,
             int K, int N, long long sA, long long sB, long long sC)
{
    constexpr int T_AH = 0;
    constexpr int T_AL = ATILB;                       // unused if !ASPLIT
    constexpr int T_BH = ASPLIT ? 2 * ATILB : ATILB;
    constexpr int T_BL = T_BH + BTILB;
    constexpr int STG  = T_BL + BTILB;                // stage bytes

    extern __shared__ char smc[];
    const uint32_t sb = smem_u32(smc);

    const int tid  = threadIdx.x;
    const int wid  = tid >> 5;
    const int lane = tid & 31;
    const int g    = lane >> 2;
    const int tg   = lane & 3;
    const int wm   = (wid >> 3) * 64;   // 0 / 64
    const int wn   = (wid & 7) * 32;    // 0..224

    const long long aoff = blockIdx.z * sA + (long long)(blockIdx.y * 128) * K;
    const long long boff = blockIdx.z * sB + (long long)(blockIdx.x * 256) * K;
    const float* Ah = Ahg + aoff;
    const float* Al = Alg + aoff;
    const float* Bh = Bhg + boff;
    const float* Bl = Blg + boff;

    float acc[4][4][4];
#pragma unroll
    for (int mt = 0; mt < 4; ++mt)
#pragma unroll
        for (int nt = 0; nt < 4; ++nt)
#pragma unroll
            for (int q = 0; q < 4; ++q) acc[mt][nt][q] = 0.f;

    const int nc = K >> 5;
    const int lr = tid >> 3;         // 0..63
    const int lc = (tid & 7) * 4;    // 0..28

    auto stage_load = [&](int i, int s) {
        const int kt = i << 5;
        const uint32_t st = sb + (uint32_t)(s * STG);
#pragma unroll
        for (int p = 0; p < 2; ++p) {
            const int r = lr + p * 64;
            const uint32_t off = (uint32_t)((r * PAD + lc) * 4);
            const long long gi = (long long)r * K + kt + lc;
            CP_ASYNC16(st + T_AH + off, Ah + gi);
            if (ASPLIT) CP_ASYNC16(st + T_AL + off, Al + gi);
        }
#pragma unroll
        for (int p = 0; p < 4; ++p) {
            const int r = lr + p * 64;
            const uint32_t off = (uint32_t)((r * PAD + lc) * 4);
            const long long gi = (long long)r * K + kt + lc;
            CP_ASYNC16(st + T_BH + off, Bh + gi);
            CP_ASYNC16(st + T_BL + off, Bl + gi);
        }
    };

    stage_load(0, 0); CP_COMMIT();
    if (nc > 1) { stage_load(1, 1); }
    CP_COMMIT();

    for (int i = 0; i < nc; ++i) {
        if (i + 2 < nc) { CP_WAIT(1); } else { CP_WAIT(0); }
        __syncthreads();

        const char* stg = smc + (i & 1) * STG;
        const float* AHs = (const float*)(stg + T_AH);
        const float* ALs = (const float*)(stg + T_AL);
        const float* BHs = (const float*)(stg + T_BH);
        const float* BLs = (const float*)(stg + T_BL);

#pragma unroll
        for (int ks = 0; ks < 4; ++ks) {
            const int k0 = ks * 8;

            // B fragments (hi + lo) stay live across the whole ks step.
            uint32_t bhf[4][2], blf[4][2];
#pragma unroll
            for (int nt = 0; nt < 4; ++nt) {
                const int n0 = (wn + nt * 8 + g) * PAD + k0 + tg;
                bhf[nt][0] = __float_as_uint(BHs[n0]);
                bhf[nt][1] = __float_as_uint(BHs[n0 + 4]);
                blf[nt][0] = __float_as_uint(BLs[n0]);
                blf[nt][1] = __float_as_uint(BLs[n0 + 4]);
            }

            // A fragments: load hi, use for 2 terms, then overwrite with lo.
            uint32_t af[4][4];
#pragma unroll
            for (int mt = 0; mt < 4; ++mt) {
                const int r0 = wm + mt * 16 + g;
                const int i00 = r0 * PAD + k0 + tg;
                const int i10 = (r0 + 8) * PAD + k0 + tg;
                if (ASPLIT) {
                    af[mt][0] = __float_as_uint(AHs[i00]);
                    af[mt][1] = __float_as_uint(AHs[i10]);
                    af[mt][2] = __float_as_uint(AHs[i00 + 4]);
                    af[mt][3] = __float_as_uint(AHs[i10 + 4]);
                } else {
                    asm("cvt.rna.tf32.f32 %0, %1;" : "=r"(af[mt][0]) : "f"(AHs[i00]));
                    asm("cvt.rna.tf32.f32 %0, %1;" : "=r"(af[mt][1]) : "f"(AHs[i10]));
                    asm("cvt.rna.tf32.f32 %0, %1;" : "=r"(af[mt][2]) : "f"(AHs[i00 + 4]));
                    asm("cvt.rna.tf32.f32 %0, %1;" : "=r"(af[mt][3]) : "f"(AHs[i10 + 4]));
                }
            }

#pragma unroll
            for (int mt = 0; mt < 4; ++mt)
#pragma unroll
                for (int nt = 0; nt < 4; ++nt)
                    mma8(acc[mt][nt], af[mt], bhf[nt]);
            if (TERMS >= 2) {
#pragma unroll
                for (int mt = 0; mt < 4; ++mt)
#pragma unroll
                    for (int nt = 0; nt < 4; ++nt)
                        mma8(acc[mt][nt], af[mt], blf[nt]);
            }
            if (TERMS >= 3) {
#pragma unroll
                for (int mt = 0; mt < 4; ++mt) {
                    const int r0 = wm + mt * 16 + g;
                    const int i00 = r0 * PAD + k0 + tg;
                    const int i10 = (r0 + 8) * PAD + k0 + tg;
                    af[mt][0] = __float_as_uint(ALs[i00]);
                    af[mt][1] = __float_as_uint(ALs[i10]);
                    af[mt][2] = __float_as_uint(ALs[i00 + 4]);
                    af[mt][3] = __float_as_uint(ALs[i10 + 4]);
                }
#pragma unroll
                for (int mt = 0; mt < 4; ++mt)
#pragma unroll
                    for (int nt = 0; nt < 4; ++nt)
                        mma8(acc[mt][nt], af[mt], bhf[nt]);
            }
        }
        __syncthreads();
        if (i + 2 < nc) { stage_load(i + 2, i & 1); CP_COMMIT(); }
    }

    // ---- epilogue ----
    const long long crow = blockIdx.z * sC
                         + (long long)(blockIdx.y * 128 + wm) * N + blockIdx.x * 256 + wn;
    if (CSPLIT) {
        float* C  = Cg  + crow;
        float* C2 = C2g + crow;
#pragma unroll
        for (int mt = 0; mt < 4; ++mt)
#pragma unroll
            for (int nt = 0; nt < 4; ++nt) {
                const long long r0 = (long long)(mt * 16 + g) * N + nt * 8 + 2 * tg;
                const long long r1 = r0 + 8LL * N;
                float2 p0 = splitf(acc[mt][nt][0]), p1 = splitf(acc[mt][nt][1]);
                float2 p2 = splitf(acc[mt][nt][2]), p3 = splitf(acc[mt][nt][3]);
                *(float2*)&C [r0] = make_float2(p0.x, p1.x);
                *(float2*)&C2[r0] = make_float2(p0.y, p1.y);
                *(float2*)&C [r1] = make_float2(p2.x, p3.x);
                *(float2*)&C2[r1] = make_float2(p2.y, p3.y);
            }
    } else {
        float* C = Cg + crow;
#pragma unroll
        for (int mt = 0; mt < 4; ++mt)
#pragma unroll
            for (int nt = 0; nt < 4; ++nt) {
                const long long r0 = (long long)(mt * 16 + g) * N + nt * 8 + 2 * tg;
                const long long r1 = r0 + 8LL * N;
                *(float2*)&C[r0] = make_float2(acc[mt][nt][0], acc[mt][nt][1]);
                *(float2*)&C[r1] = make_float2(acc[mt][nt][2], acc[mt][nt][3]);
            }
    }
}

// ---------------- pre-split into two arrays ----------------
__global__ __launch_bounds__(256)
void split_two(const float4* __restrict__ in, float4* __restrict__ oh,
               float4* __restrict__ ol, long long n4)
{
    const long long i = (long long)blockIdx.x * blockDim.x + threadIdx.x;
    if (i >= n4) return;
    float4 v = in[i];
    float2 a = splitf(v.x), b = splitf(v.y), c = splitf(v.z), d = splitf(v.w);
    oh[i] = make_float4(a.x, b.x, c.x, d.x);
    ol[i] = make_float4(a.y, b.y, c.y, d.y);
}

// ------- transpose + split: outh/outl[c][r] = split(in[r][c]) -------
__global__ __launch_bounds__(256)
void transpose_split2(const float* __restrict__ in, float* __restrict__ outh,
                      float* __restrict__ outl, int R, int C)
{
    __shared__ float t[32][33];
    const long long zo = (long long)blockIdx.z * R * C;
    in += zo; outh += zo; outl += zo;
    const int c0 = blockIdx.x * 32, r0 = blockIdx.y * 32;
#pragma unroll
    for (int dy = 0; dy < 32; dy += 8)
        t[threadIdx.y + dy][threadIdx.x] =
            in[(long long)(r0 + threadIdx.y + dy) * C + c0 + threadIdx.x];
    __syncthreads();
#pragma unroll
    for (int dy = 0; dy < 32; dy += 8) {
        float2 s = splitf(t[threadIdx.x][threadIdx.y + dy]);
        const long long o = (long long)(c0 + threadIdx.y + dy) * R + r0 + threadIdx.x;
        outh[o] = s.x;
        outl[o] = s.y;
    }
}

// ---------------- softmax over rows of length 2048, in place ----------------
__global__ __launch_bounds__(256)
void softmax_rows(float* __restrict__ data)
{
    const int S = 2048;
    float* p = data + (long long)blockIdx.x * S;
    const int tid = threadIdx.x;

    float4 v0 = ((const float4*)p)[tid];
    float4 v1 = ((const float4*)p)[tid + 256];

    float m = fmaxf(fmaxf(fmaxf(v0.x, v0.y), fmaxf(v0.z, v0.w)),
                    fmaxf(fmaxf(v1.x, v1.y), fmaxf(v1.z, v1.w)));

    __shared__ float red[8];
#pragma unroll
    for (int o = 16; o > 0; o >>= 1) m = fmaxf(m, __shfl_xor_sync(~0u, m, o));
    if ((tid & 31) == 0) red[tid >> 5] = m;
    __syncthreads();
    {
        float t = (tid < 8) ? red[tid & 7] : -1e30f;
#pragma unroll
        for (int o = 4; o > 0; o >>= 1) t = fmaxf(t, __shfl_xor_sync(~0u, t, o));
        __syncthreads();
        if (tid == 0) red[0] = t;
        __syncthreads();
        m = red[0];
    }

    v0.x = __expf(v0.x - m); v0.y = __expf(v0.y - m);
    v0.z = __expf(v0.z - m); v0.w = __expf(v0.w - m);
    v1.x = __expf(v1.x - m); v1.y = __expf(v1.y - m);
    v1.z = __expf(v1.z - m); v1.w = __expf(v1.w - m);

    float s = v0.x + v0.y + v0.z + v0.w + v1.x + v1.y + v1.z + v1.w;
#pragma unroll
    for (int o = 16; o > 0; o >>= 1) s += __shfl_xor_sync(~0u, s, o);
    __syncthreads();
    if ((tid & 31) == 0) red[tid >> 5] = s;
    __syncthreads();
    {
        float t = (tid < 8) ? red[tid & 7] : 0.f;
#pragma unroll
        for (int o = 4; o > 0; o >>= 1) t += __shfl_xor_sync(~0u, t, o);
        __syncthreads();
        if (tid == 0) red[0] = t;
        __syncthreads();
        s = red[0];
    }

    const float inv = 1.0f / s;
    v0.x *= inv; v0.y *= inv; v0.z *= inv; v0.w *= inv;
    v1.x *= inv; v1.y *= inv; v1.z *= inv; v1.w *= inv;

    ((float4*)p)[tid]       = v0;
    ((float4*)p)[tid + 256] = v1;
}

// ---------------- launch ----------------
extern "C" void kernel_launch(void* const* d_in, const int* in_sizes, int n_in,
                              void* d_out, int out_size)
{
    const float* x = (const float*)d_in[0];   // [8,2048,1024]
    const float* w = (const float*)d_in[1];   // [1024,1024]
    float* ctx  = (float*)d_out;              // [8,2048,1024]
    float* attn = (float*)d_out + 16777216LL; // [8,2048,2048]

    float *xh, *xl, *xth, *xtl, *wth, *wtl, *xwh, *xwl;
    cudaGetSymbolAddress((void**)&xh,  g_xh);
    cudaGetSymbolAddress((void**)&xl,  g_xl);
    cudaGetSymbolAddress((void**)&xth, g_xth);
    cudaGetSymbolAddress((void**)&xtl, g_xtl);
    cudaGetSymbolAddress((void**)&wth, g_wth);
    cudaGetSymbolAddress((void**)&wtl, g_wtl);
    cudaGetSymbolAddress((void**)&xwh, g_xwh);
    cudaGetSymbolAddress((void**)&xwl, g_xwl);

    const int B = 8, S = 2048, H = 1024;

    const int SM_SPLIT = 2 * (2 * ATILB + 2 * BTILB);  // 221184
    const int SM_RAW   = 2 * (ATILB + 2 * BTILB);      // 184320
    cudaFuncSetAttribute(gemm_tc<3, true,  true >, cudaFuncAttributeMaxDynamicSharedMemorySize, SM_SPLIT);
    cudaFuncSetAttribute(gemm_tc<3, true,  false>, cudaFuncAttributeMaxDynamicSharedMemorySize, SM_SPLIT);
    cudaFuncSetAttribute(gemm_tc<2, false, false>, cudaFuncAttributeMaxDynamicSharedMemorySize, SM_RAW);

    // pre-splits
    {
        long long n4 = (long long)B * S * H / 4;
        split_two<<<(unsigned)((n4 + 255) / 256), 256>>>(
            (const float4*)x, (float4*)xh, (float4*)xl, n4);
    }
    transpose_split2<<<dim3(H / 32, S / 32, B), dim3(32, 8)>>>(x, xth, xtl, S, H);
    transpose_split2<<<dim3(H / 32, H / 32, 1), dim3(32, 8)>>>(w, wth, wtl, H, H);

    // 1) xw = x @ W -> split xwh/xwl.
    gemm_tc<3, true, true><<<dim3(H / 256, (B * S) / 128, 1), 512, SM_SPLIT>>>(
        xh, xl, wth, wtl, xwh, xwl, H, H, 0, 0, 0);

    // 2) scores = xw @ x^T -> attn buffer (per batch).
    gemm_tc<3, true, false><<<dim3(S / 256, S / 128, B), 512, SM_SPLIT>>>(
        xwh, xwl, xh, xl, attn, nullptr, H, S,
        (long long)S * H, (long long)S * H, (long long)S * S);

    // 3) softmax in place
    softmax_rows<<<B * S, 256>>>(attn);

    // 4) ctx = attn @ x. A raw (tf32 on the fly), 2 terms.
    gemm_tc<2, false, false><<<dim3(H / 256, S / 128, B), 512, SM_RAW>>>(
        attn, nullptr, xth, xtl, ctx, nullptr, S, H,
        (long long)S * S, (long long)S * H, (long long)S * H);
}

// round 8
// speedup vs baseline: 1.5940x; 1.5940x over previous
#include <cuda_runtime.h>
#include <cuda_fp16.h>
#include <cstdint>

// Bilinear attention B=8, S=2048, H=1024 fp32.
// R8: 3xFP16 split GEMMs on mma.m16n8k16.f16.f32 (2x MAC rate of tf32,
// identical 11-bit mantissa => same precision as 3xTF32).
//   h = fp16(x), m = fp16(x - h);  A@B ~= Ah@Bh + Ah@Bm + Am@Bh
// GEMM3's A = attn is pre-scaled by 2^15 before split (avoids fp16 underflow
// of tiny softmax weights); epilogue multiplies by 2^-15.

// ---------------- scratch (device globals; no allocation) ----------------
#define NBS (8ull * 2048ull * 1024ull)
#define NAT (8ull * 2048ull * 2048ull)
__device__ __half g_xh [NBS], g_xm [NBS];    // split x    [B,S,H]
__device__ __half g_xth[NBS], g_xtm[NBS];    // split x^T  [B,H,S]
__device__ __half g_wth[1024ull*1024ull], g_wtm[1024ull*1024ull];  // W^T
__device__ __half g_xwh[NBS], g_xwm[NBS];    // split xw   [B,S,H]
__device__ __half g_ath[NAT], g_atm[NAT];    // split (attn * 2^15) [B,S,S]

#define ATTN_SCALE     32768.0f
#define ATTN_INV_SCALE 3.0517578125e-05f

// ---------------- helpers ----------------
__device__ __forceinline__ uint32_t smem_u32(const void* p) {
    uint32_t a;
    asm("{ .reg .u64 t; cvta.to.shared.u64 t, %1; cvt.u32.u64 %0, t; }" : "=r"(a) : "l"(p));
    return a;
}

#define CP_ASYNC16(dst, src) \
    asm volatile("cp.async.cg.shared.global [%0], [%1], 16;" :: "r"(dst), "l"(src) : "memory")
#define CP_COMMIT() asm volatile("cp.async.commit_group;" ::: "memory")
#define CP_WAIT(n)  asm volatile("cp.async.wait_group %0;" :: "n"(n) : "memory")

__device__ __forceinline__ void split16(float v, __half& h, __half& m) {
    h = __float2half_rn(v);
    m = __float2half_rn(v - __half2float(h));
}

__device__ __forceinline__ void mma16(float* c, const uint32_t* a, const uint32_t* b) {
    asm volatile(
        "mma.sync.aligned.m16n8k16.row.col.f32.f16.f16.f32 "
        "{%0,%1,%2,%3}, {%4,%5,%6,%7}, {%8,%9}, {%0,%1,%2,%3};"
        : "+f"(c[0]), "+f"(c[1]), "+f"(c[2]), "+f"(c[3])
        : "r"(a[0]), "r"(a[1]), "r"(a[2]), "r"(a[3]), "r"(b[0]), "r"(b[1]));
}

// ---------------- GEMM: C[m,n] = alpha * sum_k A[m,k]*B[n,k] ----------------
// CTA 128x256, K-chunk 32 (2 k16 steps), 2-stage cp.async.
// 8 warps (2M x 4N), warp tile 64x64 processed as two 64x32 N-halves.
// smem tiles: rows of 32 halfs padded to stride 40 (80 B) -> 20-word row
// stride makes all 32-bit fragment loads bank-conflict-free.
#define AST   40
#define ATB   (128 * AST * 2)   // 10240 B
#define BTB   (256 * AST * 2)   // 20480 B
#define T_AH  0
#define T_AM  ATB
#define T_BH  (2 * ATB)
#define T_BM  (2 * ATB + BTB)
#define STG   (2 * ATB + 2 * BTB)   // 61440 B per stage

template <bool CSPLIT>
__global__ __launch_bounds__(256, 1)
void gemm_fp16(const __half* __restrict__ Ahg, const __half* __restrict__ Amg,
               const __half* __restrict__ Bhg, const __half* __restrict__ Bmg,
               float* __restrict__ Cg, __half* __restrict__ Chg, __half* __restrict__ Cmg,
               int K, int N, long long sA, long long sB, long long sC, float alpha)
{
    extern __shared__ char smc[];
    const uint32_t sb = smem_u32(smc);

    const int tid  = threadIdx.x;
    const int wid  = tid >> 5;
    const int lane = tid & 31;
    const int g    = lane >> 2;
    const int tg   = lane & 3;
    const int wm   = (wid >> 2) * 64;   // 0 / 64
    const int wn   = (wid & 3) * 64;    // 0 / 64 / 128 / 192

    const long long aoff = blockIdx.z * sA + (long long)(blockIdx.y * 128) * K;
    const long long boff = blockIdx.z * sB + (long long)(blockIdx.x * 256) * K;
    const __half* Ah = Ahg + aoff;
    const __half* Am = Amg + aoff;
    const __half* Bh = Bhg + boff;
    const __half* Bm = Bmg + boff;

    float acc[4][8][4];
#pragma unroll
    for (int mt = 0; mt < 4; ++mt)
#pragma unroll
        for (int nt = 0; nt < 8; ++nt)
#pragma unroll
            for (int q = 0; q < 4; ++q) acc[mt][nt][q] = 0.f;

    const int nc = K >> 5;

    auto stage_load = [&](int i, int s) {
        const int kt = i << 5;
        const uint32_t st = sb + (uint32_t)(s * STG);
        // A tiles: 128 rows x 32 halfs = 64 B/row -> 4 x 16B per row, 512 ops
#pragma unroll
        for (int p = 0; p < 2; ++p) {
            const int o = tid + p * 256;
            const int r = o >> 2;
            const int c = (o & 3) * 8;                 // half offset
            const uint32_t off = (uint32_t)(r * (AST * 2) + (o & 3) * 16);
            const long long gi = (long long)r * K + kt + c;
            CP_ASYNC16(st + T_AH + off, Ah + gi);
            CP_ASYNC16(st + T_AM + off, Am + gi);
        }
        // B tiles: 256 rows -> 1024 ops
#pragma unroll
        for (int p = 0; p < 4; ++p) {
            const int o = tid + p * 256;
            const int r = o >> 2;
            const int c = (o & 3) * 8;
            const uint32_t off = (uint32_t)(r * (AST * 2) + (o & 3) * 16);
            const long long gi = (long long)r * K + kt + c;
            CP_ASYNC16(st + T_BH + off, Bh + gi);
            CP_ASYNC16(st + T_BM + off, Bm + gi);
        }
    };

    stage_load(0, 0); CP_COMMIT();
    if (nc > 1) { stage_load(1, 1); }
    CP_COMMIT();

    for (int i = 0; i < nc; ++i) {
        if (i + 2 < nc) { CP_WAIT(1); } else { CP_WAIT(0); }
        __syncthreads();

        const char* stg = smc + (i & 1) * STG;
        const __half* AHs = (const __half*)(stg + T_AH);
        const __half* AMs = (const __half*)(stg + T_AM);
        const __half* BHs = (const __half*)(stg + T_BH);
        const __half* BMs = (const __half*)(stg + T_BM);

#pragma unroll
        for (int ks = 0; ks < 2; ++ks) {
            const int k0 = ks * 16;

            // A fragments (hi and mid), live across both N-halves
            uint32_t ah[4][4], am[4][4];
#pragma unroll
            for (int mt = 0; mt < 4; ++mt) {
                const int r0 = wm + mt * 16 + g;
                const int i00 = r0 * AST + k0 + 2 * tg;
                const int i10 = (r0 + 8) * AST + k0 + 2 * tg;
                ah[mt][0] = *(const uint32_t*)(AHs + i00);
                ah[mt][1] = *(const uint32_t*)(AHs + i10);
                ah[mt][2] = *(const uint32_t*)(AHs + i00 + 8);
                ah[mt][3] = *(const uint32_t*)(AHs + i10 + 8);
                am[mt][0] = *(const uint32_t*)(AMs + i00);
                am[mt][1] = *(const uint32_t*)(AMs + i10);
                am[mt][2] = *(const uint32_t*)(AMs + i00 + 8);
                am[mt][3] = *(const uint32_t*)(AMs + i10 + 8);
            }

#pragma unroll
            for (int h2 = 0; h2 < 2; ++h2) {
                uint32_t bh[4][2], bm[4][2];
#pragma unroll
                for (int nt = 0; nt < 4; ++nt) {
                    const int n0 = (wn + h2 * 32 + nt * 8 + g) * AST + k0 + 2 * tg;
                    bh[nt][0] = *(const uint32_t*)(BHs + n0);
                    bh[nt][1] = *(const uint32_t*)(BHs + n0 + 8);
                    bm[nt][0] = *(const uint32_t*)(BMs + n0);
                    bm[nt][1] = *(const uint32_t*)(BMs + n0 + 8);
                }
#pragma unroll
                for (int mt = 0; mt < 4; ++mt)
#pragma unroll
                    for (int nt = 0; nt < 4; ++nt)
                        mma16(acc[mt][h2 * 4 + nt], ah[mt], bh[nt]);
#pragma unroll
                for (int mt = 0; mt < 4; ++mt)
#pragma unroll
                    for (int nt = 0; nt < 4; ++nt)
                        mma16(acc[mt][h2 * 4 + nt], ah[mt], bm[nt]);
#pragma unroll
                for (int mt = 0; mt < 4; ++mt)
#pragma unroll
                    for (int nt = 0; nt < 4; ++nt)
                        mma16(acc[mt][h2 * 4 + nt], am[mt], bh[nt]);
            }
        }
        __syncthreads();
        if (i + 2 < nc) { stage_load(i + 2, i & 1); CP_COMMIT(); }
    }

    // ---- epilogue ----
    const long long crow = blockIdx.z * sC
                         + (long long)(blockIdx.y * 128 + wm) * N + blockIdx.x * 256 + wn;
    if (CSPLIT) {
        __half* Ch = Chg + crow;
        __half* Cm = Cmg + crow;
#pragma unroll
        for (int mt = 0; mt < 4; ++mt)
#pragma unroll
            for (int nt = 0; nt < 8; ++nt) {
                const long long r0 = (long long)(mt * 16 + g) * N + nt * 8 + 2 * tg;
                const long long r1 = r0 + 8LL * N;
                __half h0, m0, h1, m1, h2v, m2, h3, m3;
                split16(acc[mt][nt][0], h0, m0);
                split16(acc[mt][nt][1], h1, m1);
                split16(acc[mt][nt][2], h2v, m2);
                split16(acc[mt][nt][3], h3, m3);
                *(half2*)&Ch[r0] = __halves2half2(h0, h1);
                *(half2*)&Cm[r0] = __halves2half2(m0, m1);
                *(half2*)&Ch[r1] = __halves2half2(h2v, h3);
                *(half2*)&Cm[r1] = __halves2half2(m2, m3);
            }
    } else {
        float* C = Cg + crow;
#pragma unroll
        for (int mt = 0; mt < 4; ++mt)
#pragma unroll
            for (int nt = 0; nt < 8; ++nt) {
                const long long r0 = (long long)(mt * 16 + g) * N + nt * 8 + 2 * tg;
                const long long r1 = r0 + 8LL * N;
                *(float2*)&C[r0] = make_float2(acc[mt][nt][0] * alpha, acc[mt][nt][1] * alpha);
                *(float2*)&C[r1] = make_float2(acc[mt][nt][2] * alpha, acc[mt][nt][3] * alpha);
            }
    }
}

// ---------------- pre-split into two half arrays ----------------
__global__ __launch_bounds__(256)
void split_two(const float4* __restrict__ in, __half* __restrict__ oh,
               __half* __restrict__ om, long long n4)
{
    const long long i = (long long)blockIdx.x * blockDim.x + threadIdx.x;
    if (i >= n4) return;
    float4 v = in[i];
    __half h0, m0, h1, m1, h2, m2, h3, m3;
    split16(v.x, h0, m0); split16(v.y, h1, m1);
    split16(v.z, h2, m2); split16(v.w, h3, m3);
    *(half2*)&oh[4 * i]     = __halves2half2(h0, h1);
    *(half2*)&oh[4 * i + 2] = __halves2half2(h2, h3);
    *(half2*)&om[4 * i]     = __halves2half2(m0, m1);
    *(half2*)&om[4 * i + 2] = __halves2half2(m2, m3);
}

// ------- transpose + split: outh/outm[c][r] = split(in[r][c]) -------
__global__ __launch_bounds__(256)
void transpose_split2(const float* __restrict__ in, __half* __restrict__ outh,
                      __half* __restrict__ outm, int R, int C)
{
    __shared__ float t[32][33];
    const long long zo = (long long)blockIdx.z * R * C;
    in += zo; outh += zo; outm += zo;
    const int c0 = blockIdx.x * 32, r0 = blockIdx.y * 32;
#pragma unroll
    for (int dy = 0; dy < 32; dy += 8)
        t[threadIdx.y + dy][threadIdx.x] =
            in[(long long)(r0 + threadIdx.y + dy) * C + c0 + threadIdx.x];
    __syncthreads();
#pragma unroll
    for (int dy = 0; dy < 32; dy += 8) {
        __half h, m;
        split16(t[threadIdx.x][threadIdx.y + dy], h, m);
        const long long o = (long long)(c0 + threadIdx.y + dy) * R + r0 + threadIdx.x;
        outh[o] = h;
        outm[o] = m;
    }
}

// ------- softmax over rows of 2048, in place; also emits split(attn*2^15) ---
__global__ __launch_bounds__(256)
void softmax_rows(float* __restrict__ data, __half* __restrict__ ah,
                  __half* __restrict__ am)
{
    const int S = 2048;
    const long long row = blockIdx.x;
    float* p = data + row * S;
    const int tid = threadIdx.x;

    float4 v0 = ((const float4*)p)[tid];
    float4 v1 = ((const float4*)p)[tid + 256];

    float m = fmaxf(fmaxf(fmaxf(v0.x, v0.y), fmaxf(v0.z, v0.w)),
                    fmaxf(fmaxf(v1.x, v1.y), fmaxf(v1.z, v1.w)));

    __shared__ float red[8];
#pragma unroll
    for (int o = 16; o > 0; o >>= 1) m = fmaxf(m, __shfl_xor_sync(~0u, m, o));
    if ((tid & 31) == 0) red[tid >> 5] = m;
    __syncthreads();
    {
        float t = (tid < 8) ? red[tid & 7] : -1e30f;
#pragma unroll
        for (int o = 4; o > 0; o >>= 1) t = fmaxf(t, __shfl_xor_sync(~0u, t, o));
        __syncthreads();
        if (tid == 0) red[0] = t;
        __syncthreads();
        m = red[0];
    }

    v0.x = __expf(v0.x - m); v0.y = __expf(v0.y - m);
    v0.z = __expf(v0.z - m); v0.w = __expf(v0.w - m);
    v1.x = __expf(v1.x - m); v1.y = __expf(v1.y - m);
    v1.z = __expf(v1.z - m); v1.w = __expf(v1.w - m);

    float s = v0.x + v0.y + v0.z + v0.w + v1.x + v1.y + v1.z + v1.w;
#pragma unroll
    for (int o = 16; o > 0; o >>= 1) s += __shfl_xor_sync(~0u, s, o);
    __syncthreads();
    if ((tid & 31) == 0) red[tid >> 5] = s;
    __syncthreads();
    {
        float t = (tid < 8) ? red[tid & 7] : 0.f;
#pragma unroll
        for (int o = 4; o > 0; o >>= 1) t += __shfl_xor_sync(~0u, t, o);
        __syncthreads();
        if (tid == 0) red[0] = t;
        __syncthreads();
        s = red[0];
    }

    const float inv = 1.0f / s;
    v0.x *= inv; v0.y *= inv; v0.z *= inv; v0.w *= inv;
    v1.x *= inv; v1.y *= inv; v1.z *= inv; v1.w *= inv;

    ((float4*)p)[tid]       = v0;
    ((float4*)p)[tid + 256] = v1;

    // split(attn * 2^15) for GEMM3
    __half* ahr = ah + row * S;
    __half* amr = am + row * S;
    const float sc = ATTN_SCALE * inv;   // fold scale into normalization
    float a[8] = {v0.x / inv * 0.f, 0, 0, 0, 0, 0, 0, 0};  // placeholder (unused)
    (void)a;
    {
        float f0 = v0.x * ATTN_SCALE, f1 = v0.y * ATTN_SCALE;
        float f2 = v0.z * ATTN_SCALE, f3 = v0.w * ATTN_SCALE;
        __half h0, m0, h1, m1, h2, m2, h3, m3;
        split16(f0, h0, m0); split16(f1, h1, m1);
        split16(f2, h2, m2); split16(f3, h3, m3);
        *(half2*)&ahr[4 * tid]     = __halves2half2(h0, h1);
        *(half2*)&ahr[4 * tid + 2] = __halves2half2(h2, h3);
        *(half2*)&amr[4 * tid]     = __halves2half2(m0, m1);
        *(half2*)&amr[4 * tid + 2] = __halves2half2(m2, m3);
    }
    {
        const int o = 1024 + 4 * tid;
        float f0 = v1.x * ATTN_SCALE, f1 = v1.y * ATTN_SCALE;
        float f2 = v1.z * ATTN_SCALE, f3 = v1.w * ATTN_SCALE;
        __half h0, m0, h1, m1, h2, m2, h3, m3;
        split16(f0, h0, m0); split16(f1, h1, m1);
        split16(f2, h2, m2); split16(f3, h3, m3);
        *(half2*)&ahr[o]     = __halves2half2(h0, h1);
        *(half2*)&ahr[o + 2] = __halves2half2(h2, h3);
        *(half2*)&amr[o]     = __halves2half2(m0, m1);
        *(half2*)&amr[o + 2] = __halves2half2(m2, m3);
    }
    (void)sc;
}

// ---------------- launch ----------------
extern "C" void kernel_launch(void* const* d_in, const int* in_sizes, int n_in,
                              void* d_out, int out_size)
{
    const float* x = (const float*)d_in[0];   // [8,2048,1024]
    const float* w = (const float*)d_in[1];   // [1024,1024]
    float* ctx  = (float*)d_out;              // [8,2048,1024]
    float* attn = (float*)d_out + 16777216LL; // [8,2048,2048]

    __half *xh, *xm, *xth, *xtm, *wth, *wtm, *xwh, *xwm, *ath, *atm;
    cudaGetSymbolAddress((void**)&xh,  g_xh);
    cudaGetSymbolAddress((void**)&xm,  g_xm);
    cudaGetSymbolAddress((void**)&xth, g_xth);
    cudaGetSymbolAddress((void**)&xtm, g_xtm);
    cudaGetSymbolAddress((void**)&wth, g_wth);
    cudaGetSymbolAddress((void**)&wtm, g_wtm);
    cudaGetSymbolAddress((void**)&xwh, g_xwh);
    cudaGetSymbolAddress((void**)&xwm, g_xwm);
    cudaGetSymbolAddress((void**)&ath, g_ath);
    cudaGetSymbolAddress((void**)&atm, g_atm);

    const int B = 8, S = 2048, H = 1024;

    const int SM_BYTES = 2 * STG;   // 122880
    cudaFuncSetAttribute(gemm_fp16<true >, cudaFuncAttributeMaxDynamicSharedMemorySize, SM_BYTES);
    cudaFuncSetAttribute(gemm_fp16<false>, cudaFuncAttributeMaxDynamicSharedMemorySize, SM_BYTES);

    // pre-splits
    {
        long long n4 = (long long)B * S * H / 4;
        split_two<<<(unsigned)((n4 + 255) / 256), 256>>>((const float4*)x, xh, xm, n4);
    }
    transpose_split2<<<dim3(H / 32, S / 32, B), dim3(32, 8)>>>(x, xth, xtm, S, H);
    transpose_split2<<<dim3(H / 32, H / 32, 1), dim3(32, 8)>>>(w, wth, wtm, H, H);

    // 1) xw = x @ W -> split xwh/xwm
    gemm_fp16<true><<<dim3(H / 256, (B * S) / 128, 1), 256, SM_BYTES>>>(
        xh, xm, wth, wtm, nullptr, xwh, xwm, H, H, 0, 0, 0, 1.0f);

    // 2) scores = xw @ x^T -> attn buffer (fp32)
    gemm_fp16<false><<<dim3(S / 256, S / 128, B), 256, SM_BYTES>>>(
        xwh, xwm, xh, xm, attn, nullptr, nullptr, H, S,
        (long long)S * H, (long long)S * H, (long long)S * S, 1.0f);

    // 3) softmax in place; emit split(attn * 2^15)
    softmax_rows<<<B * S, 256>>>(attn, ath, atm);

    // 4) ctx = 2^-15 * (attn*2^15) @ x
    gemm_fp16<false><<<dim3(H / 256, S / 128, B), 256, SM_BYTES>>>(
        ath, atm, xth, xtm, ctx, nullptr, nullptr, S, H,
        (long long)S * S, (long long)S * H, (long long)S * H, ATTN_INV_SCALE);
}